// round 6
// baseline (speedup 1.0000x reference)
#include <cuda_runtime.h>

// out[oc,h,w] = sum_{k,ic} w[oc,k,ic] * xr[ic, (h-1)%14, w+k-1]  (zero pad on w+k-1)
// xr[ic,hh,j] = x[ic,hh,(j-1)%14] (W-roll); output H-roll folded into reading
// x row (h-1)%14 for output row h.
//
// Grid (14 h, 32 oc) x 512 threads: ic = tid&127, cg = tid>>7 selects 3-4 output
// columns (wi ranges 0-3 / 4-6 / 7-9 / 10-13). Two-stage smem tree reduction.

__global__ __launch_bounds__(512, 2)
void rolled_conv_kernel(const float* __restrict__ x,
                        const float* __restrict__ w,
                        float* __restrict__ out) {
    __shared__ float part[128][16];   // column index = wi + (wi>=7): pad col 7 unused... (15 used)
    __shared__ float part2[8][14];

    const int h  = blockIdx.x;          // output row 0..13
    const int oc = blockIdx.y;          // 0..31
    const int ic = threadIdx.x & 127;   // input channel
    const int cg = threadIdx.x >> 7;    // column group 0..3

    const int hm1 = (h + 13) % 14;      // x row feeding this output row

    // x row: 14 floats; offset ic*196 + hm1*14 even -> 7x LDG.64
    const float2* xr2 = reinterpret_cast<const float2*>(x + ic * 196 + hm1 * 14);
    float xrow[14];
#pragma unroll
    for (int j = 0; j < 7; j++) {
        float2 v = __ldg(xr2 + j);
        xrow[2 * j]     = v.x;
        xrow[2 * j + 1] = v.y;
    }

    // w[oc][k][ic]: contiguous in ic -> coalesced per warp
    const float w0 = __ldg(w + oc * 384 + 0 * 128 + ic);
    const float w1 = __ldg(w + oc * 384 + 1 * 128 + ic);
    const float w2 = __ldg(w + oc * 384 + 2 * 128 + ic);

    // One output-column partial; all indices compile-time per branch.
#define COLPART(wi, dst)                                              \
    {                                                                 \
        float a = w1 * xrow[((wi) + 13) % 14];                        \
        if ((wi) >= 1)  a += w0 * xrow[((wi) + 12) % 14];             \
        if ((wi) <= 12) a += w2 * xrow[(wi)];                         \
        dst = a;                                                      \
    }

    float* row = &part[ic][0];
    if (cg == 0) {                       // wi 0..3 -> cols 0..3 (float4-aligned)
        float a0, a1, a2, a3;
        COLPART(0, a0) COLPART(1, a1) COLPART(2, a2) COLPART(3, a3)
        reinterpret_cast<float4*>(row)[0] = make_float4(a0, a1, a2, a3);
    } else if (cg == 1) {                // wi 4..6 -> cols 4..6
        float a4, a5, a6;
        COLPART(4, a4) COLPART(5, a5) COLPART(6, a6)
        reinterpret_cast<float2*>(row + 4)[0] = make_float2(a4, a5);
        row[6] = a6;
    } else if (cg == 2) {                // wi 7..9 -> cols 8..10 (skip pad col 7)
        float a7, a8, a9;
        COLPART(7, a7) COLPART(8, a8) COLPART(9, a9)
        reinterpret_cast<float2*>(row + 8)[0] = make_float2(a7, a8);
        row[10] = a9;
    } else {                             // wi 10..13 -> cols 11..14
        float aa, ab, ac, ad;
        COLPART(10, aa) COLPART(11, ab) COLPART(12, ac) COLPART(13, ad)
        row[11] = aa;
        reinterpret_cast<float2*>(row + 12)[0] = make_float2(ab, ac);
        row[14] = ad;
    }
#undef COLPART
    __syncthreads();

    // Stage 2: 112 threads; thread t = g*14 + wi sums ic in [g*16, g*16+16)
    if (threadIdx.x < 112) {
        const int g   = threadIdx.x / 14;
        const int wi  = threadIdx.x % 14;
        const int col = wi + (wi >= 7 ? 1 : 0);       // skip pad col 7
        const int base = g * 16;
        float v[16];
#pragma unroll
        for (int j = 0; j < 16; j++) v[j] = part[base + j][col];
        float s01 = (v[0] + v[1]) + (v[2] + v[3]);
        float s23 = (v[4] + v[5]) + (v[6] + v[7]);
        float s45 = (v[8] + v[9]) + (v[10] + v[11]);
        float s67 = (v[12] + v[13]) + (v[14] + v[15]);
        part2[g][wi] = (s01 + s23) + (s45 + s67);
    }
    __syncthreads();

    // Stage 3: 14 threads sum the 8 group partials and store
    if (threadIdx.x < 14) {
        const int wi = threadIdx.x;
        float s = ((part2[0][wi] + part2[1][wi]) + (part2[2][wi] + part2[3][wi]))
                + ((part2[4][wi] + part2[5][wi]) + (part2[6][wi] + part2[7][wi]));
        out[oc * 196 + h * 14 + wi] = s;
    }
}

extern "C" void kernel_launch(void* const* d_in, const int* in_sizes, int n_in,
                              void* d_out, int out_size) {
    const float* x = (const float*)d_in[0];   // (1,128,14,14) = 25088 floats
    const float* w = (const float*)d_in[1];   // (32,3,128)    = 12288 floats
    float* out = (float*)d_out;               // (1,32,14,14)  = 6272 floats

    dim3 grid(14, 32);
    rolled_conv_kernel<<<grid, 512>>>(x, w, out);
}

// round 7
// speedup vs baseline: 1.0489x; 1.0489x over previous
#include <cuda_runtime.h>

// out[oc,h,w] = sum_{k,ic} w[oc,k,ic] * xr[ic, (h-1)%14, w+k-1]  (zero pad on w+k-1)
// xr[ic,hh,j] = x[ic,hh,(j-1)%14] (W-roll); output H-roll folded into reading
// x row (h-1)%14 for output row h.
//
// Grid (14 h, 32 oc) x 256 threads: ic = tid&127, colgrp = tid>>7 (7 columns each).
// Two-stage smem tree reduction. (R5 shape — empirical optimum.)

__global__ __launch_bounds__(256, 4)
void rolled_conv_kernel(const float* __restrict__ x,
                        const float* __restrict__ w,
                        float* __restrict__ out) {
    __shared__ float part[128][16];   // cols 0-6 = cg0 (wi 0-6), cols 8-14 = cg1 (wi 7-13)
    __shared__ float part2[8][14];

    const int h  = blockIdx.x;          // output row 0..13
    const int oc = blockIdx.y;          // 0..31
    const int ic = threadIdx.x & 127;   // input channel
    const int cg = threadIdx.x >> 7;    // column group: 0 -> wi 0..6, 1 -> wi 7..13

    const int hm1 = (h + 13) % 14;      // x row feeding this output row

    // Front-batch ALL loads (3 w + 7 x2) -> MLP = 10, single latency exposure.
    const float* wp = w + oc * 384 + ic;
    const float w0 = __ldg(wp);
    const float w1 = __ldg(wp + 128);
    const float w2 = __ldg(wp + 256);

    // x row: 14 floats; offset ic*196 + hm1*14 even -> 7x LDG.64
    const float2* xr2 = reinterpret_cast<const float2*>(x + ic * 196 + hm1 * 14);
    float xrow[14];
#pragma unroll
    for (int j = 0; j < 7; j++) {
        float2 v = __ldg(xr2 + j);
        xrow[2 * j]     = v.x;
        xrow[2 * j + 1] = v.y;
    }

    float acc[7];
    if (cg == 0) {
        // wi = 0..6
#pragma unroll
        for (int i = 0; i < 7; i++) {
            const int wi = i;
            float a = w1 * xrow[(wi + 13) % 14];
            if (wi >= 1) a += w0 * xrow[(wi + 12) % 14];
            a += w2 * xrow[wi];                       // wi<=6 always valid
            acc[i] = a;
        }
    } else {
        // wi = 7..13
#pragma unroll
        for (int i = 0; i < 7; i++) {
            const int wi = 7 + i;
            float a = w1 * xrow[(wi + 13) % 14];
            a += w0 * xrow[(wi + 12) % 14];           // wi>=7 always valid
            if (wi <= 12) a += w2 * xrow[wi];
            acc[i] = a;
        }
    }

    // Stage 1: pack into smem. cg0 -> cols [0..6], cg1 -> cols [8..14]
    {
        float* dst = &part[ic][cg * 8];
        reinterpret_cast<float4*>(dst)[0] = make_float4(acc[0], acc[1], acc[2], acc[3]);
        reinterpret_cast<float2*>(dst + 4)[0] = make_float2(acc[4], acc[5]);
        dst[6] = acc[6];
    }
    __syncthreads();

    // Stage 2: 112 threads; thread t = g*14 + wi sums ic in [g*16, g*16+16)
    if (threadIdx.x < 112) {
        const int g   = threadIdx.x / 14;
        const int wi  = threadIdx.x % 14;
        const int col = wi + (wi >= 7 ? 1 : 0);       // skip pad col 7
        const float* src = &part[g * 16][col];
        float v[16];
#pragma unroll
        for (int j = 0; j < 16; j++) v[j] = src[j * 16];
        float s01 = (v[0] + v[1]) + (v[2] + v[3]);
        float s23 = (v[4] + v[5]) + (v[6] + v[7]);
        float s45 = (v[8] + v[9]) + (v[10] + v[11]);
        float s67 = (v[12] + v[13]) + (v[14] + v[15]);
        part2[g][wi] = (s01 + s23) + (s45 + s67);
    }
    __syncthreads();

    // Stage 3: 14 threads sum the 8 group partials and store
    if (threadIdx.x < 14) {
        const int wi = threadIdx.x;
        float s = ((part2[0][wi] + part2[1][wi]) + (part2[2][wi] + part2[3][wi]))
                + ((part2[4][wi] + part2[5][wi]) + (part2[6][wi] + part2[7][wi]));
        out[oc * 196 + h * 14 + wi] = s;
    }
}

extern "C" void kernel_launch(void* const* d_in, const int* in_sizes, int n_in,
                              void* d_out, int out_size) {
    const float* x = (const float*)d_in[0];   // (1,128,14,14) = 25088 floats
    const float* w = (const float*)d_in[1];   // (32,3,128)    = 12288 floats
    float* out = (float*)d_out;               // (1,32,14,14)  = 6272 floats

    dim3 grid(14, 32);
    rolled_conv_kernel<<<grid, 256>>>(x, w, out);
}

// round 8
// speedup vs baseline: 1.3413x; 1.2788x over previous
#include <cuda_runtime.h>

// out[oc,h,w] = sum_{k,ic} w[oc,k,ic] * xr[ic, (h-1)%14, w+k-1]   (zero pad on w+k-1)
// xr[ic,hh,j] = x[ic,hh,(j-1)%14] (W-roll); output H-roll folded into reading
// x row (h-1)%14 for output row h.
//
// Grid: (14 h, 32 oc) x 128 threads = ic.  (R3 shape — best measured: 5.82us.)
// Front-batched loads (MLP=10), two-stage smem tree reduction, nw=4 barriers.

__global__ __launch_bounds__(128, 8)
void rolled_conv_kernel(const float* __restrict__ x,
                        const float* __restrict__ w,
                        float* __restrict__ out) {
    __shared__ float part[128][16];   // 64B row stride -> float4-aligned
    __shared__ float part2[8][14];

    const int h  = blockIdx.x;   // output row 0..13
    const int oc = blockIdx.y;   // 0..31
    const int ic = threadIdx.x;  // 0..127

    const int hm1 = (h + 13) % 14;          // x row feeding this output row

    // Front-batch ALL loads (3 w + 7 x2) -> MLP = 10, one latency exposure.
    const float* wp = w + oc * 384 + ic;
    const float w0 = __ldg(wp);
    const float w1 = __ldg(wp + 128);
    const float w2 = __ldg(wp + 256);

    // x row: 14 floats; offset ic*196 + hm1*14 is even -> 7x LDG.64
    const float2* xr2 = reinterpret_cast<const float2*>(x + ic * 196 + hm1 * 14);
    float xrow[14];
#pragma unroll
    for (int j = 0; j < 7; j++) {
        float2 v = __ldg(xr2 + j);
        xrow[2 * j]     = v.x;
        xrow[2 * j + 1] = v.y;
    }

    // Per-channel partial for each of the 14 output columns
    float acc[14];
#pragma unroll
    for (int wi = 0; wi < 14; wi++) {
        float a = w1 * xrow[(wi + 13) % 14];          // k=1 tap (always valid)
        if (wi >= 1)  a += w0 * xrow[(wi + 12) % 14]; // k=0 tap
        if (wi <= 12) a += w2 * xrow[wi];             // k=2 tap
        acc[wi] = a;
    }

    // Stage 1: pack partials to smem (wide stores; STS is issue-only)
    {
        float4* dst4 = reinterpret_cast<float4*>(&part[ic][0]);
        dst4[0] = make_float4(acc[0],  acc[1],  acc[2],  acc[3]);
        dst4[1] = make_float4(acc[4],  acc[5],  acc[6],  acc[7]);
        dst4[2] = make_float4(acc[8],  acc[9],  acc[10], acc[11]);
        reinterpret_cast<float2*>(&part[ic][12])[0] = make_float2(acc[12], acc[13]);
    }
    __syncthreads();

    // Stage 2: 112 threads; thread t = g*14 + wi sums ic in [g*16, g*16+16)
    if (threadIdx.x < 112) {
        const int g  = threadIdx.x / 14;
        const int wi = threadIdx.x % 14;
        const float* src = &part[g * 16][wi];
        float v[16];
#pragma unroll
        for (int j = 0; j < 16; j++) v[j] = src[j * 16];
        float s01 = (v[0] + v[1]) + (v[2] + v[3]);
        float s23 = (v[4] + v[5]) + (v[6] + v[7]);
        float s45 = (v[8] + v[9]) + (v[10] + v[11]);
        float s67 = (v[12] + v[13]) + (v[14] + v[15]);
        part2[g][wi] = (s01 + s23) + (s45 + s67);
    }
    __syncthreads();

    // Stage 3: 14 threads sum the 8 group partials and store
    if (threadIdx.x < 14) {
        const int wi = threadIdx.x;
        float s = ((part2[0][wi] + part2[1][wi]) + (part2[2][wi] + part2[3][wi]))
                + ((part2[4][wi] + part2[5][wi]) + (part2[6][wi] + part2[7][wi]));
        out[oc * 196 + h * 14 + wi] = s;
    }
}

extern "C" void kernel_launch(void* const* d_in, const int* in_sizes, int n_in,
                              void* d_out, int out_size) {
    const float* x = (const float*)d_in[0];   // (1,128,14,14) = 25088 floats
    const float* w = (const float*)d_in[1];   // (32,3,128)    = 12288 floats
    float* out = (float*)d_out;               // (1,32,14,14)  = 6272 floats

    dim3 grid(14, 32);
    rolled_conv_kernel<<<grid, 128>>>(x, w, out);
}

// round 9
// speedup vs baseline: 1.3478x; 1.0048x over previous
#include <cuda_runtime.h>

// out[oc,h,w] = sum_{k,ic} w[oc,k,ic] * xr[ic, (h-1)%14, w+k-1]   (zero pad on w+k-1)
// xr[ic,hh,j] = x[ic,hh,(j-1)%14] (W-roll); output H-roll folded into reading
// x row (h-1)%14 for output row h.
//
// Grid: (14 h, 32 oc) x 128 threads = ic.  (Best measured shape: 5.63us kernel.)
// Front-batched loads (MLP=10), two-stage smem tree reduction; stage-2 uses
// power-of-two 8x16 thread mapping (no integer div/mod).

__global__ __launch_bounds__(128, 8)
void rolled_conv_kernel(const float* __restrict__ x,
                        const float* __restrict__ w,
                        float* __restrict__ out) {
    __shared__ float part[128][16];   // 64B row stride -> float4-aligned
    __shared__ float part2[8][14];

    const int h  = blockIdx.x;   // output row 0..13
    const int oc = blockIdx.y;   // 0..31
    const int ic = threadIdx.x;  // 0..127

    const int hm1 = (h + 13) % 14;          // x row feeding this output row

    // Front-batch ALL loads (3 w + 7 x2) -> MLP = 10, one latency exposure.
    const float* wp = w + oc * 384 + ic;
    const float w0 = __ldg(wp);
    const float w1 = __ldg(wp + 128);
    const float w2 = __ldg(wp + 256);

    // x row: 14 floats; offset ic*196 + hm1*14 is even -> 7x LDG.64
    const float2* xr2 = reinterpret_cast<const float2*>(x + ic * 196 + hm1 * 14);
    float xrow[14];
#pragma unroll
    for (int j = 0; j < 7; j++) {
        float2 v = __ldg(xr2 + j);
        xrow[2 * j]     = v.x;
        xrow[2 * j + 1] = v.y;
    }

    // Per-channel partial for each of the 14 output columns
    float acc[14];
#pragma unroll
    for (int wi = 0; wi < 14; wi++) {
        float a = w1 * xrow[(wi + 13) % 14];          // k=1 tap (always valid)
        if (wi >= 1)  a += w0 * xrow[(wi + 12) % 14]; // k=0 tap
        if (wi <= 12) a += w2 * xrow[wi];             // k=2 tap
        acc[wi] = a;
    }

    // Stage 1: pack partials to smem (wide stores; STS is issue-only)
    {
        float4* dst4 = reinterpret_cast<float4*>(&part[ic][0]);
        dst4[0] = make_float4(acc[0],  acc[1],  acc[2],  acc[3]);
        dst4[1] = make_float4(acc[4],  acc[5],  acc[6],  acc[7]);
        dst4[2] = make_float4(acc[8],  acc[9],  acc[10], acc[11]);
        reinterpret_cast<float2*>(&part[ic][12])[0] = make_float2(acc[12], acc[13]);
    }
    __syncthreads();

    // Stage 2: 8x16 mapping, pure bitops: g = tid>>4 (ic group), wi = tid&15.
    {
        const int g  = threadIdx.x >> 4;
        const int wi = threadIdx.x & 15;
        if (wi < 14) {
            const float* src = &part[g * 16][wi];
            float v[16];
#pragma unroll
            for (int j = 0; j < 16; j++) v[j] = src[j * 16];
            float s01 = (v[0] + v[1]) + (v[2] + v[3]);
            float s23 = (v[4] + v[5]) + (v[6] + v[7]);
            float s45 = (v[8] + v[9]) + (v[10] + v[11]);
            float s67 = (v[12] + v[13]) + (v[14] + v[15]);
            part2[g][wi] = (s01 + s23) + (s45 + s67);
        }
    }
    __syncthreads();

    // Stage 3: 14 threads sum the 8 group partials and store
    if (threadIdx.x < 14) {
        const int wi = threadIdx.x;
        float s = ((part2[0][wi] + part2[1][wi]) + (part2[2][wi] + part2[3][wi]))
                + ((part2[4][wi] + part2[5][wi]) + (part2[6][wi] + part2[7][wi]));
        out[oc * 196 + h * 14 + wi] = s;
    }
}

extern "C" void kernel_launch(void* const* d_in, const int* in_sizes, int n_in,
                              void* d_out, int out_size) {
    const float* x = (const float*)d_in[0];   // (1,128,14,14) = 25088 floats
    const float* w = (const float*)d_in[1];   // (32,3,128)    = 12288 floats
    float* out = (float*)d_out;               // (1,32,14,14)  = 6272 floats

    dim3 grid(14, 32);
    rolled_conv_kernel<<<grid, 128>>>(x, w, out);
}